// round 13
// baseline (speedup 1.0000x reference)
#include <cuda_runtime.h>
#include <cuda_bf16.h>
#include <cuda_fp16.h>
#include <math.h>
#include <stdint.h>

#define B_ 1024
#define N_ 49
#define E_ 2048
#define D_ 512
#define A_ 512
#define M_ (B_ * N_)   // 50176

// out layout: [awe B*E][alpha B*N][beta B]
#define AWE_OFF   0
#define ALPHA_OFF (B_ * E_)
#define BETA_OFF  (ALPHA_OFF + B_ * N_)

// scratch (device globals)
__device__ float g_att2[B_ * A_];                 // [B, A] = att2 + b_dec + b_enc
__device__ float g_attp[4 * M_];                  // 4 a-chunk partials of att[m]
__device__ __half g_Wf[A_ * E_];                  // W_enc fp16
__device__ __half g_encf[(size_t)M_ * E_];        // encoder_out fp16

// ---------------------------------------------------------------------------
__device__ __forceinline__ uint32_t smem_u32(const void* p) {
    return (uint32_t)__cvta_generic_to_shared((void*)p);
}
__device__ __forceinline__ void cpasync16(uint32_t dst, const void* src) {
    asm volatile("cp.async.cg.shared.global [%0], [%1], 16;" :: "r"(dst), "l"(src));
}
__device__ __forceinline__ void ldsm4(uint32_t* r, uint32_t addr) {
    asm volatile("ldmatrix.sync.aligned.m8n8.x4.shared.b16 {%0,%1,%2,%3}, [%4];"
                 : "=r"(r[0]), "=r"(r[1]), "=r"(r[2]), "=r"(r[3]) : "r"(addr));
}
__device__ __forceinline__ void mma16816(float* c, const uint32_t* a, const uint32_t* b) {
    asm("mma.sync.aligned.m16n8k16.row.col.f32.f16.f16.f32 "
        "{%0,%1,%2,%3}, {%4,%5,%6,%7}, {%8,%9}, {%0,%1,%2,%3};"
        : "+f"(c[0]), "+f"(c[1]), "+f"(c[2]), "+f"(c[3])
        : "r"(a[0]), "r"(a[1]), "r"(a[2]), "r"(a[3]), "r"(b[0]), "r"(b[1]));
}

// ---------------------------------------------------------------------------
// Kernel 1 (fused prep): enc->fp16, W_enc->fp16, att2 GEMM.
//  blocks [0, ENC_BLKS): convert encoder_out (2048 halves/block)
//  blocks [ENC_BLKS, +W_BLKS): convert W_enc (1024 halves/block)
//  blocks [ENC_BLKS+W_BLKS, +128): att2 (64 b-groups x 2 a-halves)
// ---------------------------------------------------------------------------
#define ENC_BLKS ((M_ * E_) / 2048)    // 50176
#define W_BLKS   ((A_ * E_) / 1024)    // 1024

__global__ __launch_bounds__(256)
void k_prep(const float* __restrict__ enc, const float* __restrict__ W,
            const float* __restrict__ dh, const float* __restrict__ Wdec,
            const float* __restrict__ b_enc, const float* __restrict__ b_dec)
{
    __shared__ float dhs[16][D_];
    const int bid = blockIdx.x;
    const int t = threadIdx.x;

    if (bid < ENC_BLKS) {
        const size_t i = ((size_t)bid * 256 + t) * 8;
        const float4 x = *(const float4*)(enc + i);
        const float4 y = *(const float4*)(enc + i + 4);
        uint4 v;
        __half2 h;
        h = __floats2half2_rn(x.x, x.y); v.x = *(uint32_t*)&h;
        h = __floats2half2_rn(x.z, x.w); v.y = *(uint32_t*)&h;
        h = __floats2half2_rn(y.x, y.y); v.z = *(uint32_t*)&h;
        h = __floats2half2_rn(y.z, y.w); v.w = *(uint32_t*)&h;
        *(uint4*)(g_encf + i) = v;
        return;
    }
    if (bid < ENC_BLKS + W_BLKS) {
        const int i = ((bid - ENC_BLKS) * 256 + t) * 4;
        const float4 x = *(const float4*)(W + i);
        ((__half2*)g_Wf)[i / 2]     = __floats2half2_rn(x.x, x.y);
        ((__half2*)g_Wf)[i / 2 + 1] = __floats2half2_rn(x.z, x.w);
        return;
    }

    // ---- att2 ----
    const int idx = bid - ENC_BLKS - W_BLKS;     // 0..127
    const int b0 = (idx >> 1) * 16;
    const int a = (idx & 1) * 256 + t;
    for (int i = t; i < 16 * D_; i += 256)
        dhs[i >> 9][i & 511] = dh[(size_t)b0 * D_ + i];
    __syncthreads();

    const float bias = b_dec[a] + b_enc[a];
    float acc[16];
    #pragma unroll
    for (int j = 0; j < 16; j++) acc[j] = 0.f;
    const float* w = Wdec + (size_t)a * D_;
    for (int k = 0; k < D_; k += 4) {
        const float4 wv = *(const float4*)(w + k);
        #pragma unroll
        for (int j = 0; j < 16; j++) {
            acc[j] = fmaf(wv.x, dhs[j][k + 0],
                     fmaf(wv.y, dhs[j][k + 1],
                     fmaf(wv.z, dhs[j][k + 2],
                     fmaf(wv.w, dhs[j][k + 3], acc[j]))));
        }
    }
    #pragma unroll
    for (int j = 0; j < 16; j++)
        g_att2[(size_t)(b0 + j) * A_ + a] = acc[j] + bias;
}

// ---------------------------------------------------------------------------
// Kernel 2: single-term fp16 HMMA GEMM, both operands via cp.async.
//  Tile 128x128, BK=32, 4 stages (wait_group 2), 2 CTAs/SM, warp tile 64x32.
// ---------------------------------------------------------------------------
#define BM 128
#define BK 32
#define NCHUNK (E_ / BK)     // 64
#define ROWB 80              // padded row bytes (32 fp16 = 64B -> 80B)

#define SM_ATT2   0          // 4*128*4 = 2048
#define SM_WF     2048       // 128*4 = 512
#define SM_RED    2560       // 128*4*4 = 2048
#define SM_STAGE0 5120
#define AF_OFF    0          // 128*80 = 10240
#define BF_OFF    10240      // 128*80 = 10240
#define STG       20480
#define NSTAGE    4
#define SMEM_TOTAL (SM_STAGE0 + NSTAGE * STG)   // 87040

__global__ __launch_bounds__(256, 2)
void k_main(const float* __restrict__ Wfull)
{
    extern __shared__ char smem[];
    const int t = threadIdx.x;
    const int lane = t & 31, wid = t >> 5;
    const int warp_m = wid & 1, warp_n = wid >> 1;
    const int chunkA = blockIdx.x;         // 0..3
    const int m0 = blockIdx.y * BM;
    const int a0 = chunkA * 128;
    const uint32_t sbase = smem_u32(smem);

    // epilogue constants
    const int b_first = m0 / N_;
    {
        float* att2s = (float*)(smem + SM_ATT2);
        for (int i = t; i < 4 * 128; i += 256) {
            const int br = b_first + (i >> 7);
            att2s[i] = (br < B_) ? g_att2[(size_t)br * A_ + a0 + (i & 127)] : 0.f;
        }
        if (t < 128) ((float*)(smem + SM_WF))[t] = Wfull[a0 + t];
    }

    // ---- async loaders ----
    const int lrow = t >> 2, lu = t & 3;
    auto cpA = [&](int c, int st) {
        const uint32_t af = sbase + SM_STAGE0 + st * STG + AF_OFF;
        #pragma unroll
        for (int i = 0; i < 2; i++) {
            const int row = lrow + 64 * i;
            cpasync16(af + (uint32_t)(row * ROWB + lu * 16),
                      g_encf + (size_t)(m0 + row) * E_ + c * BK + lu * 8);
        }
    };
    auto cpB = [&](int c, int st) {
        const uint32_t bf = sbase + SM_STAGE0 + st * STG + BF_OFF;
        #pragma unroll
        for (int i = 0; i < 2; i++) {
            const int row = lrow + 64 * i;
            cpasync16(bf + (uint32_t)(row * ROWB + lu * 16),
                      g_Wf + (size_t)(a0 + row) * E_ + c * BK + lu * 8);
        }
    };

    float acc[4][4][4];
    #pragma unroll
    for (int i = 0; i < 4; i++)
        #pragma unroll
        for (int j = 0; j < 4; j++)
            #pragma unroll
            for (int q = 0; q < 4; q++) acc[i][j][q] = 0.f;

    // ---- prologue: fill stages 0..2 ----
    cpA(0, 0); cpB(0, 0);
    asm volatile("cp.async.commit_group;" ::: "memory");
    cpA(1, 1); cpB(1, 1);
    asm volatile("cp.async.commit_group;" ::: "memory");
    cpA(2, 2); cpB(2, 2);
    asm volatile("cp.async.commit_group;" ::: "memory");
    __syncthreads();   // also covers att2s/wf fill

    int st_c = 0;
    // ---- pipeline ----
    for (int c = 0; c < NCHUNK; c++) {
        asm volatile("cp.async.wait_group 2;" ::: "memory");
        __syncthreads();

        if (c + 3 < NCHUNK) {
            const int st_f = (st_c + 3) & 3;
            cpA(c + 3, st_f); cpB(c + 3, st_f);
        }
        asm volatile("cp.async.commit_group;" ::: "memory");

        const uint32_t abase = sbase + SM_STAGE0 + st_c * STG;
        #pragma unroll
        for (int ks = 0; ks < 2; ks++) {
            uint32_t af[4][4], bf[4][2];
            #pragma unroll
            for (int mt = 0; mt < 4; mt++) {
                const uint32_t addr = abase + AF_OFF
                    + (uint32_t)((warp_m * 64 + mt * 16 + (lane & 15)) * ROWB)
                    + (uint32_t)((lane >> 4) * 16 + ks * 32);
                ldsm4(af[mt], addr);
            }
            #pragma unroll
            for (int pt = 0; pt < 2; pt++) {
                const uint32_t row = (uint32_t)(warp_n * 32 + pt * 16
                                   + ((lane >> 4) << 3) + (lane & 7));
                const uint32_t addr = abase + BF_OFF + (uint32_t)(row * ROWB)
                    + (uint32_t)(((lane >> 3) & 1) * 16 + ks * 32);
                uint32_t r[4];
                ldsm4(r, addr);
                bf[2 * pt][0] = r[0]; bf[2 * pt][1] = r[1];
                bf[2 * pt + 1][0] = r[2]; bf[2 * pt + 1][1] = r[3];
            }
            #pragma unroll
            for (int mt = 0; mt < 4; mt++)
                #pragma unroll
                for (int nt = 0; nt < 4; nt++)
                    mma16816(acc[mt][nt], af[mt], bf[nt]);
        }
        st_c = (st_c + 1) & 3;
    }

    // ---- epilogue ----
    const float* att2s = (const float*)(smem + SM_ATT2);
    const float* wfs   = (const float*)(smem + SM_WF);
    float* red         = (float*)(smem + SM_RED);   // [128][4]

    #pragma unroll
    for (int mt = 0; mt < 4; mt++) {
        const int r0 = warp_m * 64 + mt * 16 + (lane >> 2);
        const int r1 = r0 + 8;
        const int bl0 = (m0 + r0) / N_ - b_first;
        const int bl1 = (m0 + r1) / N_ - b_first;
        float s0 = 0.f, s1 = 0.f;
        #pragma unroll
        for (int nt = 0; nt < 4; nt++) {
            const int cb = warp_n * 32 + nt * 8 + (lane & 3) * 2;
            float v;
            v = fmaxf(acc[mt][nt][0] + att2s[bl0 * 128 + cb],     0.f); s0 = fmaf(v, wfs[cb],     s0);
            v = fmaxf(acc[mt][nt][1] + att2s[bl0 * 128 + cb + 1], 0.f); s0 = fmaf(v, wfs[cb + 1], s0);
            v = fmaxf(acc[mt][nt][2] + att2s[bl1 * 128 + cb],     0.f); s1 = fmaf(v, wfs[cb],     s1);
            v = fmaxf(acc[mt][nt][3] + att2s[bl1 * 128 + cb + 1], 0.f); s1 = fmaf(v, wfs[cb + 1], s1);
        }
        s0 += __shfl_xor_sync(0xffffffffu, s0, 1);
        s0 += __shfl_xor_sync(0xffffffffu, s0, 2);
        s1 += __shfl_xor_sync(0xffffffffu, s1, 1);
        s1 += __shfl_xor_sync(0xffffffffu, s1, 2);
        if ((lane & 3) == 0) {
            red[r0 * 4 + warp_n] = s0;
            red[r1 * 4 + warp_n] = s1;
        }
    }
    __syncthreads();
    if (t < 128) {
        const float s = red[t * 4] + red[t * 4 + 1] + red[t * 4 + 2] + red[t * 4 + 3];
        g_attp[(size_t)chunkA * M_ + m0 + t] = s;
    }
}

// ---------------------------------------------------------------------------
// Kernel 3: beta, softmax*beta, awe from fp16 enc, final writes.
// ---------------------------------------------------------------------------
__global__ __launch_bounds__(256)
void k_final(const float* __restrict__ dh,
             const float* __restrict__ Wsig, const float* __restrict__ bsig,
             const float* __restrict__ bfull, float* __restrict__ out)
{
    const int b = blockIdx.x;
    const int t = threadIdx.x;
    __shared__ float dhs[D_];
    __shared__ float red[256];
    __shared__ float alph[N_];
    __shared__ float beta_s;

    for (int i = t; i < D_; i += 256) dhs[i] = dh[(size_t)b * D_ + i];
    __syncthreads();

    red[t] = dhs[t] * Wsig[t] + dhs[t + 256] * Wsig[t + 256];
    __syncthreads();
    for (int s = 128; s > 0; s >>= 1) {
        if (t < s) red[t] += red[t + s];
        __syncthreads();
    }
    if (t == 0) beta_s = 1.f / (1.f + expf(-(red[0] + bsig[0])));

    if (t < N_) {
        float v = bfull[0];
        #pragma unroll
        for (int c = 0; c < 4; c++) v += g_attp[(size_t)c * M_ + b * N_ + t];
        alph[t] = v;
    }
    __syncthreads();

    if (t == 0) {
        float mx = -1e30f;
        for (int n = 0; n < N_; n++) mx = fmaxf(mx, alph[n]);
        float sm = 0.f;
        for (int n = 0; n < N_; n++) { float e = expf(alph[n] - mx); alph[n] = e; sm += e; }
        const float scale = beta_s / sm;
        for (int n = 0; n < N_; n++) alph[n] *= scale;
    }
    __syncthreads();

    if (t < N_) out[ALPHA_OFF + b * N_ + t] = alph[t];
    if (t == 0) out[BETA_OFF + b] = beta_s;

    // awe from fp16 enc: each thread owns 8 contiguous e (one uint4 per n)
    const uint4* eb = (const uint4*)(g_encf + (size_t)b * N_ * E_);
    const int col = t;   // uint4 index within a row of 256
    float s[8];
    #pragma unroll
    for (int q = 0; q < 8; q++) s[q] = 0.f;
    #pragma unroll 7
    for (int n = 0; n < N_; n++) {
        const float al = alph[n];
        const uint4 v = eb[n * 256 + col];
        const __half2* hp = (const __half2*)&v;
        #pragma unroll
        for (int q = 0; q < 4; q++) {
            const float2 f = __half22float2(hp[q]);
            s[2 * q]     = fmaf(al, f.x, s[2 * q]);
            s[2 * q + 1] = fmaf(al, f.y, s[2 * q + 1]);
        }
    }
    float4* o4 = (float4*)(out + AWE_OFF + (size_t)b * E_ + col * 8);
    o4[0] = make_float4(s[0], s[1], s[2], s[3]);
    o4[1] = make_float4(s[4], s[5], s[6], s[7]);
}

// ---------------------------------------------------------------------------
extern "C" void kernel_launch(void* const* d_in, const int* in_sizes, int n_in,
                              void* d_out, int out_size)
{
    (void)in_sizes; (void)n_in; (void)out_size;
    const float* enc  = (const float*)d_in[0];
    const float* dh   = (const float*)d_in[1];
    const float* Wenc = (const float*)d_in[2];
    const float* benc = (const float*)d_in[3];
    const float* Wdec = (const float*)d_in[4];
    const float* bdec = (const float*)d_in[5];
    const float* Wsig = (const float*)d_in[6];
    const float* bsig = (const float*)d_in[7];
    const float* Wful = (const float*)d_in[8];
    const float* bful = (const float*)d_in[9];
    float* out = (float*)d_out;

    cudaFuncSetAttribute(k_main, cudaFuncAttributeMaxDynamicSharedMemorySize, SMEM_TOTAL);

    k_prep<<<ENC_BLKS + W_BLKS + 128, 256>>>(enc, Wenc, dh, Wdec, benc, bdec);
    k_main<<<dim3(4, M_ / BM), 256, SMEM_TOTAL>>>(Wful);
    k_final<<<B_, 256>>>(dh, Wsig, bsig, bful, out);
}

// round 14
// speedup vs baseline: 1.1562x; 1.1562x over previous
#include <cuda_runtime.h>
#include <cuda_bf16.h>
#include <cuda_fp16.h>
#include <math.h>
#include <stdint.h>

#define B_ 1024
#define N_ 49
#define E_ 2048
#define D_ 512
#define A_ 512
#define M_ (B_ * N_)   // 50176

// out layout: [awe B*E][alpha B*N][beta B]
#define AWE_OFF   0
#define ALPHA_OFF (B_ * E_)
#define BETA_OFF  (ALPHA_OFF + B_ * N_)

// scratch (device globals)
__device__ float g_att2[B_ * A_];                 // [B, A] = att2 + b_dec + b_enc
__device__ float g_attp[4 * M_];                  // 4 a-chunk partials of att[m]
__device__ __half g_Wf[A_ * E_];                  // W_enc fp16
__device__ __half g_encf[(size_t)M_ * E_];        // encoder_out fp16

// ---------------------------------------------------------------------------
__device__ __forceinline__ uint32_t smem_u32(const void* p) {
    return (uint32_t)__cvta_generic_to_shared((void*)p);
}
__device__ __forceinline__ void cpasync16(uint32_t dst, const void* src) {
    asm volatile("cp.async.cg.shared.global [%0], [%1], 16;" :: "r"(dst), "l"(src));
}
__device__ __forceinline__ void ldsm4(uint32_t* r, uint32_t addr) {
    asm volatile("ldmatrix.sync.aligned.m8n8.x4.shared.b16 {%0,%1,%2,%3}, [%4];"
                 : "=r"(r[0]), "=r"(r[1]), "=r"(r[2]), "=r"(r[3]) : "r"(addr));
}
__device__ __forceinline__ void mma16816(float* c, const uint32_t* a, const uint32_t* b) {
    asm("mma.sync.aligned.m16n8k16.row.col.f32.f16.f16.f32 "
        "{%0,%1,%2,%3}, {%4,%5,%6,%7}, {%8,%9}, {%0,%1,%2,%3};"
        : "+f"(c[0]), "+f"(c[1]), "+f"(c[2]), "+f"(c[3])
        : "r"(a[0]), "r"(a[1]), "r"(a[2]), "r"(a[3]), "r"(b[0]), "r"(b[1]));
}

// ---------------------------------------------------------------------------
// Kernel 0a: convert W_enc to fp16
// ---------------------------------------------------------------------------
__global__ __launch_bounds__(256)
void k_wconv(const float* __restrict__ W)
{
    const int i = (blockIdx.x * 256 + threadIdx.x) * 4;
    const float4 x = *(const float4*)(W + i);
    ((__half2*)g_Wf)[i / 2]     = __floats2half2_rn(x.x, x.y);
    ((__half2*)g_Wf)[i / 2 + 1] = __floats2half2_rn(x.z, x.w);
}

// ---------------------------------------------------------------------------
// Kernel 0b: convert encoder_out to fp16 (8 floats / thread)
// ---------------------------------------------------------------------------
__global__ __launch_bounds__(256)
void k_encconv(const float* __restrict__ e)
{
    const size_t i = ((size_t)blockIdx.x * 256 + threadIdx.x) * 8;
    const float4 x = *(const float4*)(e + i);
    const float4 y = *(const float4*)(e + i + 4);
    uint4 v;
    __half2 h;
    h = __floats2half2_rn(x.x, x.y); v.x = *(uint32_t*)&h;
    h = __floats2half2_rn(x.z, x.w); v.y = *(uint32_t*)&h;
    h = __floats2half2_rn(y.x, y.y); v.z = *(uint32_t*)&h;
    h = __floats2half2_rn(y.z, y.w); v.w = *(uint32_t*)&h;
    *(uint4*)(g_encf + i) = v;
}

// ---------------------------------------------------------------------------
// Kernel 1: att2[b,a] = dot(dh[b], W_dec[a]) + b_dec[a] + b_enc[a]
// ---------------------------------------------------------------------------
__global__ __launch_bounds__(256)
void k_att2(const float* __restrict__ dh, const float* __restrict__ Wdec,
            const float* __restrict__ b_enc, const float* __restrict__ b_dec)
{
    __shared__ float dhs[16][D_];
    const int b0 = blockIdx.x * 16;
    const int t = threadIdx.x;
    for (int i = t; i < 16 * D_; i += 256)
        dhs[i >> 9][i & 511] = dh[(size_t)b0 * D_ + i];
    __syncthreads();

    const int a = blockIdx.y * 256 + t;
    const float bias = b_dec[a] + b_enc[a];
    float acc[16];
    #pragma unroll
    for (int j = 0; j < 16; j++) acc[j] = 0.f;
    const float* w = Wdec + (size_t)a * D_;
    for (int k = 0; k < D_; k += 4) {
        const float4 wv = *(const float4*)(w + k);
        #pragma unroll
        for (int j = 0; j < 16; j++) {
            acc[j] = fmaf(wv.x, dhs[j][k + 0],
                     fmaf(wv.y, dhs[j][k + 1],
                     fmaf(wv.z, dhs[j][k + 2],
                     fmaf(wv.w, dhs[j][k + 3], acc[j]))));
        }
    }
    #pragma unroll
    for (int j = 0; j < 16; j++)
        g_att2[(size_t)(b0 + j) * A_ + a] = acc[j] + bias;
}

// ---------------------------------------------------------------------------
// Kernel 2: single-term fp16 HMMA GEMM, both operands via cp.async.
//  Tile 128x128, BK=32, 4 stages (wait_group 2), 2 CTAs/SM, warp tile 64x32.
// ---------------------------------------------------------------------------
#define BM 128
#define BK 32
#define NCHUNK (E_ / BK)     // 64
#define ROWB 80              // padded row bytes (32 fp16 = 64B -> 80B)

#define SM_ATT2   0          // 4*128*4 = 2048
#define SM_WF     2048       // 128*4 = 512
#define SM_RED    2560       // 128*4*4 = 2048
#define SM_STAGE0 5120
#define AF_OFF    0          // 128*80 = 10240
#define BF_OFF    10240      // 128*80 = 10240
#define STG       20480
#define NSTAGE    4
#define SMEM_TOTAL (SM_STAGE0 + NSTAGE * STG)   // 87040

__global__ __launch_bounds__(256, 2)
void k_main(const float* __restrict__ Wfull)
{
    extern __shared__ char smem[];
    const int t = threadIdx.x;
    const int lane = t & 31, wid = t >> 5;
    const int warp_m = wid & 1, warp_n = wid >> 1;
    const int chunkA = blockIdx.x;         // 0..3
    const int m0 = blockIdx.y * BM;
    const int a0 = chunkA * 128;
    const uint32_t sbase = smem_u32(smem);

    // epilogue constants
    const int b_first = m0 / N_;
    {
        float* att2s = (float*)(smem + SM_ATT2);
        for (int i = t; i < 4 * 128; i += 256) {
            const int br = b_first + (i >> 7);
            att2s[i] = (br < B_) ? g_att2[(size_t)br * A_ + a0 + (i & 127)] : 0.f;
        }
        if (t < 128) ((float*)(smem + SM_WF))[t] = Wfull[a0 + t];
    }

    // ---- async loaders ----
    const int lrow = t >> 2, lu = t & 3;
    auto cpA = [&](int c, int st) {
        const uint32_t af = sbase + SM_STAGE0 + st * STG + AF_OFF;
        #pragma unroll
        for (int i = 0; i < 2; i++) {
            const int row = lrow + 64 * i;
            cpasync16(af + (uint32_t)(row * ROWB + lu * 16),
                      g_encf + (size_t)(m0 + row) * E_ + c * BK + lu * 8);
        }
    };
    auto cpB = [&](int c, int st) {
        const uint32_t bf = sbase + SM_STAGE0 + st * STG + BF_OFF;
        #pragma unroll
        for (int i = 0; i < 2; i++) {
            const int row = lrow + 64 * i;
            cpasync16(bf + (uint32_t)(row * ROWB + lu * 16),
                      g_Wf + (size_t)(a0 + row) * E_ + c * BK + lu * 8);
        }
    };

    float acc[4][4][4];
    #pragma unroll
    for (int i = 0; i < 4; i++)
        #pragma unroll
        for (int j = 0; j < 4; j++)
            #pragma unroll
            for (int q = 0; q < 4; q++) acc[i][j][q] = 0.f;

    // ---- prologue: fill stages 0..2 ----
    cpA(0, 0); cpB(0, 0);
    asm volatile("cp.async.commit_group;" ::: "memory");
    cpA(1, 1); cpB(1, 1);
    asm volatile("cp.async.commit_group;" ::: "memory");
    cpA(2, 2); cpB(2, 2);
    asm volatile("cp.async.commit_group;" ::: "memory");
    __syncthreads();   // also covers att2s/wf fill

    int st_c = 0;
    // ---- pipeline ----
    for (int c = 0; c < NCHUNK; c++) {
        asm volatile("cp.async.wait_group 2;" ::: "memory");
        __syncthreads();

        if (c + 3 < NCHUNK) {
            const int st_f = (st_c + 3) & 3;
            cpA(c + 3, st_f); cpB(c + 3, st_f);
        }
        asm volatile("cp.async.commit_group;" ::: "memory");

        const uint32_t abase = sbase + SM_STAGE0 + st_c * STG;
        #pragma unroll
        for (int ks = 0; ks < 2; ks++) {
            uint32_t af[4][4], bf[4][2];
            #pragma unroll
            for (int mt = 0; mt < 4; mt++) {
                const uint32_t addr = abase + AF_OFF
                    + (uint32_t)((warp_m * 64 + mt * 16 + (lane & 15)) * ROWB)
                    + (uint32_t)((lane >> 4) * 16 + ks * 32);
                ldsm4(af[mt], addr);
            }
            #pragma unroll
            for (int pt = 0; pt < 2; pt++) {
                const uint32_t row = (uint32_t)(warp_n * 32 + pt * 16
                                   + ((lane >> 4) << 3) + (lane & 7));
                const uint32_t addr = abase + BF_OFF + (uint32_t)(row * ROWB)
                    + (uint32_t)(((lane >> 3) & 1) * 16 + ks * 32);
                uint32_t r[4];
                ldsm4(r, addr);
                bf[2 * pt][0] = r[0]; bf[2 * pt][1] = r[1];
                bf[2 * pt + 1][0] = r[2]; bf[2 * pt + 1][1] = r[3];
            }
            #pragma unroll
            for (int mt = 0; mt < 4; mt++)
                #pragma unroll
                for (int nt = 0; nt < 4; nt++)
                    mma16816(acc[mt][nt], af[mt], bf[nt]);
        }
        st_c = (st_c + 1) & 3;
    }

    // ---- epilogue ----
    const float* att2s = (const float*)(smem + SM_ATT2);
    const float* wfs   = (const float*)(smem + SM_WF);
    float* red         = (float*)(smem + SM_RED);   // [128][4]

    #pragma unroll
    for (int mt = 0; mt < 4; mt++) {
        const int r0 = warp_m * 64 + mt * 16 + (lane >> 2);
        const int r1 = r0 + 8;
        const int bl0 = (m0 + r0) / N_ - b_first;
        const int bl1 = (m0 + r1) / N_ - b_first;
        float s0 = 0.f, s1 = 0.f;
        #pragma unroll
        for (int nt = 0; nt < 4; nt++) {
            const int cb = warp_n * 32 + nt * 8 + (lane & 3) * 2;
            float v;
            v = fmaxf(acc[mt][nt][0] + att2s[bl0 * 128 + cb],     0.f); s0 = fmaf(v, wfs[cb],     s0);
            v = fmaxf(acc[mt][nt][1] + att2s[bl0 * 128 + cb + 1], 0.f); s0 = fmaf(v, wfs[cb + 1], s0);
            v = fmaxf(acc[mt][nt][2] + att2s[bl1 * 128 + cb],     0.f); s1 = fmaf(v, wfs[cb],     s1);
            v = fmaxf(acc[mt][nt][3] + att2s[bl1 * 128 + cb + 1], 0.f); s1 = fmaf(v, wfs[cb + 1], s1);
        }
        s0 += __shfl_xor_sync(0xffffffffu, s0, 1);
        s0 += __shfl_xor_sync(0xffffffffu, s0, 2);
        s1 += __shfl_xor_sync(0xffffffffu, s1, 1);
        s1 += __shfl_xor_sync(0xffffffffu, s1, 2);
        if ((lane & 3) == 0) {
            red[r0 * 4 + warp_n] = s0;
            red[r1 * 4 + warp_n] = s1;
        }
    }
    __syncthreads();
    if (t < 128) {
        const float s = red[t * 4] + red[t * 4 + 1] + red[t * 4 + 2] + red[t * 4 + 3];
        g_attp[(size_t)chunkA * M_ + m0 + t] = s;
    }
}

// ---------------------------------------------------------------------------
// Kernel 3: beta, softmax*beta, awe from fp16 enc, final writes.
// ---------------------------------------------------------------------------
__global__ __launch_bounds__(256)
void k_final(const float* __restrict__ dh,
             const float* __restrict__ Wsig, const float* __restrict__ bsig,
             const float* __restrict__ bfull, float* __restrict__ out)
{
    const int b = blockIdx.x;
    const int t = threadIdx.x;
    __shared__ float dhs[D_];
    __shared__ float red[256];
    __shared__ float alph[N_];
    __shared__ float beta_s;

    for (int i = t; i < D_; i += 256) dhs[i] = dh[(size_t)b * D_ + i];
    __syncthreads();

    red[t] = dhs[t] * Wsig[t] + dhs[t + 256] * Wsig[t + 256];
    __syncthreads();
    for (int s = 128; s > 0; s >>= 1) {
        if (t < s) red[t] += red[t + s];
        __syncthreads();
    }
    if (t == 0) beta_s = 1.f / (1.f + expf(-(red[0] + bsig[0])));

    if (t < N_) {
        float v = bfull[0];
        #pragma unroll
        for (int c = 0; c < 4; c++) v += g_attp[(size_t)c * M_ + b * N_ + t];
        alph[t] = v;
    }
    __syncthreads();

    if (t == 0) {
        float mx = -1e30f;
        for (int n = 0; n < N_; n++) mx = fmaxf(mx, alph[n]);
        float sm = 0.f;
        for (int n = 0; n < N_; n++) { float e = expf(alph[n] - mx); alph[n] = e; sm += e; }
        const float scale = beta_s / sm;
        for (int n = 0; n < N_; n++) alph[n] *= scale;
    }
    __syncthreads();

    if (t < N_) out[ALPHA_OFF + b * N_ + t] = alph[t];
    if (t == 0) out[BETA_OFF + b] = beta_s;

    // awe from fp16 enc: each thread owns 8 contiguous e (one uint4 per n)
    const uint4* eb = (const uint4*)(g_encf + (size_t)b * N_ * E_);
    const int col = t;   // uint4 index within a row of 256
    float s[8];
    #pragma unroll
    for (int q = 0; q < 8; q++) s[q] = 0.f;
    #pragma unroll 7
    for (int n = 0; n < N_; n++) {
        const float al = alph[n];
        const uint4 v = eb[n * 256 + col];
        const __half2* hp = (const __half2*)&v;
        #pragma unroll
        for (int q = 0; q < 4; q++) {
            const float2 f = __half22float2(hp[q]);
            s[2 * q]     = fmaf(al, f.x, s[2 * q]);
            s[2 * q + 1] = fmaf(al, f.y, s[2 * q + 1]);
        }
    }
    float4* o4 = (float4*)(out + AWE_OFF + (size_t)b * E_ + col * 8);
    o4[0] = make_float4(s[0], s[1], s[2], s[3]);
    o4[1] = make_float4(s[4], s[5], s[6], s[7]);
}

// ---------------------------------------------------------------------------
extern "C" void kernel_launch(void* const* d_in, const int* in_sizes, int n_in,
                              void* d_out, int out_size)
{
    (void)in_sizes; (void)n_in; (void)out_size;
    const float* enc  = (const float*)d_in[0];
    const float* dh   = (const float*)d_in[1];
    const float* Wenc = (const float*)d_in[2];
    const float* benc = (const float*)d_in[3];
    const float* Wdec = (const float*)d_in[4];
    const float* bdec = (const float*)d_in[5];
    const float* Wsig = (const float*)d_in[6];
    const float* bsig = (const float*)d_in[7];
    const float* Wful = (const float*)d_in[8];
    const float* bful = (const float*)d_in[9];
    float* out = (float*)d_out;

    cudaFuncSetAttribute(k_main, cudaFuncAttributeMaxDynamicSharedMemorySize, SMEM_TOTAL);

    k_wconv<<<(A_ * E_) / 1024, 256>>>(Wenc);
    k_encconv<<<(int)(((size_t)M_ * E_) / 2048), 256>>>(enc);
    k_att2<<<dim3(B_ / 16, 2), 256>>>(dh, Wdec, benc, bdec);
    k_main<<<dim3(4, M_ / BM), 256, SMEM_TOTAL>>>(Wful);
    k_final<<<B_, 256>>>(dh, Wsig, bsig, bful, out);
}